// round 7
// baseline (speedup 1.0000x reference)
#include <cuda_runtime.h>
#include <cuda_bf16.h>
#include <mma.h>
#include <math.h>
#include <cstdint>

using namespace nvcuda;

#define NTOK 8192
#define DIM  1024
#define HID  4096
#define NEXP 8
#define NPAIR (NTOK*2)
#define ROWPAD 128
#define LN_EPS 1e-5f

// ---------------- scratch (device globals) ----------------
__device__ float g_topkw[NPAIR];
__device__ int   g_topki[NPAIR];
__device__ int   g_cnt[NEXP];
__device__ int   g_off[NEXP + 1];
__device__ int   g_pairs[NPAIR];
__device__ int   g_pairof[NPAIR];

__device__ __nv_bfloat16 g_xh[(size_t)(NPAIR + ROWPAD) * DIM];
__device__ __nv_bfloat16 g_xl[(size_t)(NPAIR + ROWPAD) * DIM];
__device__ __nv_bfloat16 g_hh[(size_t)(NPAIR + ROWPAD) * HID];
__device__ __nv_bfloat16 g_hl[(size_t)(NPAIR + ROWPAD) * HID];
__device__ __nv_bfloat16 g_w1h[(size_t)NEXP * HID * DIM];
__device__ __nv_bfloat16 g_w1l[(size_t)NEXP * HID * DIM];
__device__ __nv_bfloat16 g_w2h[(size_t)NEXP * DIM * HID];
__device__ __nv_bfloat16 g_w2l[(size_t)NEXP * DIM * HID];
__device__ float g_y[(size_t)NPAIR * DIM];

// ---------------- helpers ----------------
__device__ __forceinline__ void split4_store(__nv_bfloat16* hi, __nv_bfloat16* lo, float4 f) {
    float v[4] = {f.x, f.y, f.z, f.w};
    __nv_bfloat16 h[4], l[4];
#pragma unroll
    for (int u = 0; u < 4; u++) {
        h[u] = __float2bfloat16(v[u]);
        l[u] = __float2bfloat16(v[u] - __bfloat162float(h[u]));
    }
    *reinterpret_cast<__nv_bfloat162*>(hi)     = __halves2bfloat162(h[0], h[1]);
    *reinterpret_cast<__nv_bfloat162*>(hi + 2) = __halves2bfloat162(h[2], h[3]);
    *reinterpret_cast<__nv_bfloat162*>(lo)     = __halves2bfloat162(l[0], l[1]);
    *reinterpret_cast<__nv_bfloat162*>(lo + 2) = __halves2bfloat162(l[2], l[3]);
}

__device__ __forceinline__ void cpa16(void* sdst, const void* gsrc) {
    uint32_t s = (uint32_t)__cvta_generic_to_shared(sdst);
    asm volatile("cp.async.cg.shared.global [%0], [%1], 16;\n" :: "r"(s), "l"(gsrc));
}
__device__ __forceinline__ void cp_commit() { asm volatile("cp.async.commit_group;\n"); }
template <int N> __device__ __forceinline__ void cp_wait() {
    asm volatile("cp.async.wait_group %0;\n" :: "n"(N));
}

// ---------------- kernel 1: gating + (fused) W2 split ----------------
__global__ void gate_kernel(const float* __restrict__ x,
                            const float* __restrict__ gw,
                            const float* __restrict__ gb,
                            const float* __restrict__ w2) {
    int t = blockIdx.x;
    int tid = threadIdx.x;                 // 256 threads
    int wid = tid >> 5, lane = tid & 31;

    float acc[NEXP];
#pragma unroll
    for (int e = 0; e < NEXP; e++) acc[e] = 0.f;

    const float* xr = x + (size_t)t * DIM;
    for (int i = tid; i < DIM; i += 256) {
        float xv = xr[i];
#pragma unroll
        for (int e = 0; e < NEXP; e++) acc[e] += xv * gw[e * DIM + i];
    }
#pragma unroll
    for (int e = 0; e < NEXP; e++)
#pragma unroll
        for (int o = 16; o > 0; o >>= 1) acc[e] += __shfl_down_sync(0xffffffffu, acc[e], o);

    __shared__ float part[8][NEXP];
    if (lane == 0) {
#pragma unroll
        for (int e = 0; e < NEXP; e++) part[wid][e] = acc[e];
    }
    __syncthreads();

    if (tid == 0) {
        float lg[NEXP], p[NEXP];
#pragma unroll
        for (int e = 0; e < NEXP; e++) {
            float s = gb[e];
#pragma unroll
            for (int w = 0; w < 8; w++) s += part[w][e];
            lg[e] = s;
        }
        float m = lg[0];
#pragma unroll
        for (int e = 1; e < NEXP; e++) m = fmaxf(m, lg[e]);
        float se = 0.f;
#pragma unroll
        for (int e = 0; e < NEXP; e++) { p[e] = expf(lg[e] - m); se += p[e]; }
        float inv = 1.f / se;
#pragma unroll
        for (int e = 0; e < NEXP; e++) p[e] *= inv;

        int i0 = 0;
#pragma unroll
        for (int e = 1; e < NEXP; e++) if (p[e] > p[i0]) i0 = e;
        int i1 = (i0 == 0) ? 1 : 0;
#pragma unroll
        for (int e = 0; e < NEXP; e++) if (e != i0 && p[e] > p[i1]) i1 = e;

        float b = expf(p[i1] - p[i0]);
        float w0 = 1.f / (1.f + b);
        float w1 = b / (1.f + b);

        g_topki[2 * t]     = i0;  g_topki[2 * t + 1] = i1;
        g_topkw[2 * t]     = w0;  g_topkw[2 * t + 1] = w1;
    }

    // fused: split W2 (8*1024*4096 fp32 = 8388608 float4) across 8192*256 threads, 4 each
    size_t base = (size_t)blockIdx.x * 256 + tid;
#pragma unroll
    for (int rep = 0; rep < 4; rep++) {
        size_t i = base + (size_t)rep * 2097152;
        float4 f = reinterpret_cast<const float4*>(w2)[i];
        split4_store(&g_w2h[i * 4], &g_w2l[i * 4], f);
    }
}

// ---------------- kernel 2: route = count + prefix + scatter (one block) ----------------
__global__ void route_kernel() {
    __shared__ int sc[NEXP];
    __shared__ int so[NEXP];
    int tid = threadIdx.x;                 // 1024 threads
    if (tid < NEXP) sc[tid] = 0;
    __syncthreads();
    for (int i = tid; i < NPAIR; i += 1024) atomicAdd(&sc[g_topki[i]], 1);
    __syncthreads();
    if (tid == 0) {
        int s = 0;
#pragma unroll
        for (int e = 0; e < NEXP; e++) {
            so[e] = s;
            g_off[e] = s;
            g_cnt[e] = sc[e];
            s += sc[e];
        }
        g_off[NEXP] = s;
    }
    __syncthreads();
    if (tid < NEXP) sc[tid] = so[tid];     // reuse as cursors
    __syncthreads();
    for (int i = tid; i < NPAIR; i += 1024) {
        int e = g_topki[i];
        int pos = atomicAdd(&sc[e], 1);
        g_pairs[pos] = i;
        g_pairof[i] = pos;
    }
}

// ---------------- kernel 3: gather x (split to hi/lo) + (fused) W1 split ----------------
__global__ void gather_kernel(const float* __restrict__ x, const float* __restrict__ w1) {
    int pr = blockIdx.x;
    int tid = threadIdx.x;                 // 256 threads
    int tok = g_pairs[pr] >> 1;
    float4 f = reinterpret_cast<const float4*>(x + (size_t)tok * DIM)[tid];
    split4_store(&g_xh[(size_t)pr * DIM + tid * 4], &g_xl[(size_t)pr * DIM + tid * 4], f);

    // fused: split W1 (8388608 float4) across 16384*256 threads, 2 each
    size_t base = (size_t)pr * 256 + tid;
#pragma unroll
    for (int rep = 0; rep < 2; rep++) {
        size_t i = base + (size_t)rep * 4194304;
        float4 w = reinterpret_cast<const float4*>(w1)[i];
        split4_store(&g_w1h[i * 4], &g_w1l[i * 4], w);
    }
}

// ---------------- grouped GEMM: pre-split bf16 hi/lo, cp.async 3-stage pipeline ----------
// PASS1: g_h(hi/lo) = relu(Xg @ W1^T + b1)   A=g_xh/g_xl (K=1024), Nn=4096
// PASS2: g_y        =      H  @ W2^T + b2    A=g_hh/g_hl (K=4096), Nn=1024
#define BM 128
#define BN 256
#define BK 32
#define STR 48
#define STAGES 3
#define A_PL (BM * STR)            // 6144 elems
#define B_PL (BN * STR)            // 12288 elems
#define BUF_ELEMS (2 * A_PL + 2 * B_PL)       // 36864 elems = 73728 B
#define SMEM_BYTES (STAGES * BUF_ELEMS * 2)   // 221184 B

template <bool PASS1>
__global__ __launch_bounds__(256, 1)
void moe_gemm(const float* __restrict__ Bias) {
    constexpr int K  = PASS1 ? DIM : HID;
    constexpr int Nn = PASS1 ? HID : DIM;
    constexpr int KT = K / BK;
    const __nv_bfloat16* __restrict__ Agh = PASS1 ? g_xh : g_hh;
    const __nv_bfloat16* __restrict__ Agl = PASS1 ? g_xl : g_hl;
    const __nv_bfloat16* __restrict__ Wgh = PASS1 ? g_w1h : g_w2h;
    const __nv_bfloat16* __restrict__ Wgl = PASS1 ? g_w1l : g_w2l;

    int e = blockIdx.z;
    int cnt = g_cnt[e];
    int m0 = blockIdx.x * BM;
    if (m0 >= cnt) return;
    int r0 = g_off[e] + m0;
    int n0 = blockIdx.y * BN;

    const __nv_bfloat16* We_h = Wgh + (size_t)e * Nn * K;
    const __nv_bfloat16* We_l = Wgl + (size_t)e * Nn * K;
    const float* be = Bias + (size_t)e * Nn;

    extern __shared__ __align__(16) unsigned char smem_raw[];
    __nv_bfloat16* smem = reinterpret_cast<__nv_bfloat16*>(smem_raw);

    int tid = threadIdx.x;
    int wid = tid >> 5, lane = tid & 31;
    int wm = wid & 1;        // 2 warps along M (64 rows each)
    int wn = wid >> 1;       // 4 warps along N (64 cols each)

    // panel loader: 3072 x 16B chunks, 12 per thread
    auto load_panel = [&](int kt, int b) {
        const int k0 = kt * BK;
        __nv_bfloat16* bb = smem + b * BUF_ELEMS;
#pragma unroll
        for (int t = 0; t < 12; t++) {
            int id = tid + t * 256;
            if (id < 1024) {                       // A: hi then lo plane
                int plane = id >> 9, rem = id & 511;
                int row = rem >> 2, ch = rem & 3;
                const __nv_bfloat16* src =
                    (plane ? Agl : Agh) + (size_t)(r0 + row) * K + k0 + ch * 8;
                __nv_bfloat16* dst = bb + plane * A_PL + row * STR + ch * 8;
                cpa16(dst, src);
            } else {                               // B: hi then lo plane
                int id2 = id - 1024;
                int plane = id2 >> 10, rem = id2 & 1023;
                int row = rem >> 2, ch = rem & 3;
                const __nv_bfloat16* src =
                    (plane ? We_l : We_h) + (size_t)(n0 + row) * K + k0 + ch * 8;
                __nv_bfloat16* dst = bb + 2 * A_PL + plane * B_PL + row * STR + ch * 8;
                cpa16(dst, src);
            }
        }
    };

    wmma::fragment<wmma::accumulator, 16, 16, 16, float> acc[4][4];
#pragma unroll
    for (int i = 0; i < 4; i++)
#pragma unroll
        for (int j = 0; j < 4; j++) wmma::fill_fragment(acc[i][j], 0.f);

    load_panel(0, 0); cp_commit();
    load_panel(1, 1); cp_commit();

    for (int kt = 0; kt < KT; kt++) {
        // prefetch kt+2 (empty commit group at tail keeps the group count aligned)
        if (kt + 2 < KT) load_panel(kt + 2, (kt + 2) % STAGES);
        cp_commit();
        cp_wait<2>();            // group kt complete
        __syncthreads();

        const __nv_bfloat16* bAh = smem + (kt % STAGES) * BUF_ELEMS;
        const __nv_bfloat16* bAl = bAh + A_PL;
        const __nv_bfloat16* bBh = bAh + 2 * A_PL;
        const __nv_bfloat16* bBl = bBh + B_PL;

#pragma unroll
        for (int kk = 0; kk < 2; kk++) {
            wmma::fragment<wmma::matrix_a, 16, 16, 16, __nv_bfloat16, wmma::row_major> ah[4], al[4];
#pragma unroll
            for (int i = 0; i < 4; i++) {
                wmma::load_matrix_sync(ah[i], bAh + (wm * 64 + i * 16) * STR + kk * 16, STR);
                wmma::load_matrix_sync(al[i], bAl + (wm * 64 + i * 16) * STR + kk * 16, STR);
            }
#pragma unroll
            for (int j = 0; j < 4; j++) {
                wmma::fragment<wmma::matrix_b, 16, 16, 16, __nv_bfloat16, wmma::col_major> bh, bl;
                wmma::load_matrix_sync(bh, bBh + (wn * 64 + j * 16) * STR + kk * 16, STR);
                wmma::load_matrix_sync(bl, bBl + (wn * 64 + j * 16) * STR + kk * 16, STR);
#pragma unroll
                for (int i = 0; i < 4; i++) {
                    wmma::mma_sync(acc[i][j], ah[i], bh, acc[i][j]);
                    wmma::mma_sync(acc[i][j], ah[i], bl, acc[i][j]);
                    wmma::mma_sync(acc[i][j], al[i], bh, acc[i][j]);
                }
            }
        }
        __syncthreads();   // buffer kt free for the kt+3 load issued next iteration
    }

    // epilogue: per-warp 64x64 stage in smem
    float* stage = reinterpret_cast<float*>(smem_raw) + (size_t)wid * 4096;
#pragma unroll
    for (int i = 0; i < 4; i++)
#pragma unroll
        for (int j = 0; j < 4; j++)
            wmma::store_matrix_sync(stage + i * 16 * 64 + j * 16, acc[i][j], 64,
                                    wmma::mem_row_major);
    __syncwarp();

    int rem = cnt - m0;   // valid rows in this tile
    for (int it = lane; it < 1024; it += 32) {    // 64x64 elems as float4
        int row_loc = it >> 4;
        int c4 = (it & 15) * 4;
        int rtile = wm * 64 + row_loc;
        if (rtile < rem) {
            float4 v = *reinterpret_cast<float4*>(stage + row_loc * 64 + c4);
            int gcol = n0 + wn * 64 + c4;
            float4 bv = *reinterpret_cast<const float4*>(&be[gcol]);
            v.x += bv.x; v.y += bv.y; v.z += bv.z; v.w += bv.w;
            size_t grow = (size_t)(r0 + rtile);
            if (PASS1) {
                v.x = fmaxf(v.x, 0.f); v.y = fmaxf(v.y, 0.f);
                v.z = fmaxf(v.z, 0.f); v.w = fmaxf(v.w, 0.f);
                split4_store(&g_hh[grow * HID + gcol], &g_hl[grow * HID + gcol], v);
            } else {
                *reinterpret_cast<float4*>(&g_y[grow * DIM + gcol]) = v;
            }
        }
    }
}

// ---------------- kernel 6: combine + residual + LayerNorm ----------------
__global__ void finalize_kernel(const float* __restrict__ x,
                                const float* __restrict__ lnw,
                                const float* __restrict__ lnb,
                                float* __restrict__ out) {
    int t = blockIdx.x;
    int tid = threadIdx.x;
    int wid = tid >> 5, lane = tid & 31;

    float w0 = g_topkw[2 * t], w1 = g_topkw[2 * t + 1];
    size_t p0 = (size_t)g_pairof[2 * t] * DIM;
    size_t p1 = (size_t)g_pairof[2 * t + 1] * DIM;

    __shared__ float r[DIM];
    __shared__ float ps[8][2];

    float s = 0.f, s2 = 0.f;
    for (int i = tid; i < DIM; i += 256) {
        float v = x[(size_t)t * DIM + i] + w0 * g_y[p0 + i] + w1 * g_y[p1 + i];
        r[i] = v;
        s += v;
        s2 += v * v;
    }
#pragma unroll
    for (int o = 16; o > 0; o >>= 1) {
        s  += __shfl_down_sync(0xffffffffu, s, o);
        s2 += __shfl_down_sync(0xffffffffu, s2, o);
    }
    if (lane == 0) { ps[wid][0] = s; ps[wid][1] = s2; }
    __syncthreads();
    if (tid == 0) {
        float a = 0.f, b = 0.f;
#pragma unroll
        for (int w = 0; w < 8; w++) { a += ps[w][0]; b += ps[w][1]; }
        float mu = a / (float)DIM;
        float var = b / (float)DIM - mu * mu;
        ps[0][0] = mu;
        ps[0][1] = rsqrtf(var + LN_EPS);
    }
    __syncthreads();
    float mu = ps[0][0], inv = ps[0][1];
    for (int i = tid; i < DIM; i += 256)
        out[(size_t)t * DIM + i] = (r[i] - mu) * inv * lnw[i] + lnb[i];
}

// ---------------- launch ----------------
extern "C" void kernel_launch(void* const* d_in, const int* in_sizes, int n_in,
                              void* d_out, int out_size) {
    (void)in_sizes; (void)n_in; (void)out_size;
    const float* x   = (const float*)d_in[0];
    const float* gw  = (const float*)d_in[1];
    const float* gb  = (const float*)d_in[2];
    const float* w1  = (const float*)d_in[3];
    const float* b1  = (const float*)d_in[4];
    const float* w2  = (const float*)d_in[5];
    const float* b2  = (const float*)d_in[6];
    const float* lnw = (const float*)d_in[7];
    const float* lnb = (const float*)d_in[8];
    float* out = (float*)d_out;

    cudaFuncSetAttribute(moe_gemm<true>,  cudaFuncAttributeMaxDynamicSharedMemorySize, SMEM_BYTES);
    cudaFuncSetAttribute(moe_gemm<false>, cudaFuncAttributeMaxDynamicSharedMemorySize, SMEM_BYTES);

    gate_kernel<<<NTOK, 256>>>(x, gw, gb, w2);                         // launch 0 (+W2 split)
    route_kernel<<<1, 1024>>>();                                       // launch 1
    gather_kernel<<<NPAIR, 256>>>(x, w1);                              // launch 2 (+W1 split)
    moe_gemm<true><<<dim3(NPAIR / BM, HID / BN, NEXP), 256, SMEM_BYTES>>>(b1);   // launch 3 <- ncu
    moe_gemm<false><<<dim3(NPAIR / BM, DIM / BN, NEXP), 256, SMEM_BYTES>>>(b2);  // launch 4
    finalize_kernel<<<NTOK, 256>>>(x, lnw, lnb, out);                  // launch 5
}

// round 9
// speedup vs baseline: 1.1258x; 1.1258x over previous
#include <cuda_runtime.h>
#include <cuda_bf16.h>
#include <mma.h>
#include <math.h>
#include <cstdint>

using namespace nvcuda;

#define NTOK 8192
#define DIM  1024
#define HID  4096
#define NEXP 8
#define NPAIR (NTOK*2)
#define ROWPAD 128
#define LN_EPS 1e-5f

// ---------------- scratch (device globals) ----------------
__device__ float g_topkw[NPAIR];
__device__ int   g_topki[NPAIR];
__device__ int   g_cnt[NEXP];
__device__ int   g_off[NEXP + 1];
__device__ int   g_pairs[NPAIR];
__device__ int   g_pairof[NPAIR];

__device__ __nv_bfloat16 g_xh[(size_t)(NPAIR + ROWPAD) * DIM];
__device__ __nv_bfloat16 g_xl[(size_t)(NPAIR + ROWPAD) * DIM];
__device__ __nv_bfloat16 g_hh[(size_t)(NPAIR + ROWPAD) * HID];
__device__ __nv_bfloat16 g_hl[(size_t)(NPAIR + ROWPAD) * HID];
__device__ __nv_bfloat16 g_w1h[(size_t)NEXP * HID * DIM];
__device__ __nv_bfloat16 g_w1l[(size_t)NEXP * HID * DIM];
__device__ __nv_bfloat16 g_w2h[(size_t)NEXP * DIM * HID];
__device__ __nv_bfloat16 g_w2l[(size_t)NEXP * DIM * HID];
__device__ float g_y[(size_t)NPAIR * DIM];

// ---------------- helpers ----------------
__device__ __forceinline__ void split4_store(__nv_bfloat16* hi, __nv_bfloat16* lo, float4 f) {
    float v[4] = {f.x, f.y, f.z, f.w};
    __nv_bfloat16 h[4], l[4];
#pragma unroll
    for (int u = 0; u < 4; u++) {
        h[u] = __float2bfloat16(v[u]);
        l[u] = __float2bfloat16(v[u] - __bfloat162float(h[u]));
    }
    *reinterpret_cast<__nv_bfloat162*>(hi)     = __halves2bfloat162(h[0], h[1]);
    *reinterpret_cast<__nv_bfloat162*>(hi + 2) = __halves2bfloat162(h[2], h[3]);
    *reinterpret_cast<__nv_bfloat162*>(lo)     = __halves2bfloat162(l[0], l[1]);
    *reinterpret_cast<__nv_bfloat162*>(lo + 2) = __halves2bfloat162(l[2], l[3]);
}

__device__ __forceinline__ void cpa16(void* sdst, const void* gsrc) {
    uint32_t s = (uint32_t)__cvta_generic_to_shared(sdst);
    asm volatile("cp.async.cg.shared.global [%0], [%1], 16;\n" :: "r"(s), "l"(gsrc));
}
__device__ __forceinline__ void cp_commit() { asm volatile("cp.async.commit_group;\n"); }
template <int N> __device__ __forceinline__ void cp_wait() {
    asm volatile("cp.async.wait_group %0;\n" :: "n"(N));
}

// ---------------- kernel 1: gating + (fused) W2 split ----------------
__global__ void gate_kernel(const float* __restrict__ x,
                            const float* __restrict__ gw,
                            const float* __restrict__ gb,
                            const float* __restrict__ w2) {
    int t = blockIdx.x;
    int tid = threadIdx.x;                 // 256 threads
    int wid = tid >> 5, lane = tid & 31;

    float acc[NEXP];
#pragma unroll
    for (int e = 0; e < NEXP; e++) acc[e] = 0.f;

    const float* xr = x + (size_t)t * DIM;
    for (int i = tid; i < DIM; i += 256) {
        float xv = xr[i];
#pragma unroll
        for (int e = 0; e < NEXP; e++) acc[e] += xv * gw[e * DIM + i];
    }
#pragma unroll
    for (int e = 0; e < NEXP; e++)
#pragma unroll
        for (int o = 16; o > 0; o >>= 1) acc[e] += __shfl_down_sync(0xffffffffu, acc[e], o);

    __shared__ float part[8][NEXP];
    if (lane == 0) {
#pragma unroll
        for (int e = 0; e < NEXP; e++) part[wid][e] = acc[e];
    }
    __syncthreads();

    if (tid == 0) {
        float lg[NEXP], p[NEXP];
#pragma unroll
        for (int e = 0; e < NEXP; e++) {
            float s = gb[e];
#pragma unroll
            for (int w = 0; w < 8; w++) s += part[w][e];
            lg[e] = s;
        }
        float m = lg[0];
#pragma unroll
        for (int e = 1; e < NEXP; e++) m = fmaxf(m, lg[e]);
        float se = 0.f;
#pragma unroll
        for (int e = 0; e < NEXP; e++) { p[e] = expf(lg[e] - m); se += p[e]; }
        float inv = 1.f / se;
#pragma unroll
        for (int e = 0; e < NEXP; e++) p[e] *= inv;

        int i0 = 0;
#pragma unroll
        for (int e = 1; e < NEXP; e++) if (p[e] > p[i0]) i0 = e;
        int i1 = (i0 == 0) ? 1 : 0;
#pragma unroll
        for (int e = 0; e < NEXP; e++) if (e != i0 && p[e] > p[i1]) i1 = e;

        float b = expf(p[i1] - p[i0]);
        float w0 = 1.f / (1.f + b);
        float w1 = b / (1.f + b);

        g_topki[2 * t]     = i0;  g_topki[2 * t + 1] = i1;
        g_topkw[2 * t]     = w0;  g_topkw[2 * t + 1] = w1;
    }

    // fused: split W2 (8388608 float4) across 8192*256 threads, 4 each
    size_t base = (size_t)blockIdx.x * 256 + tid;
#pragma unroll
    for (int rep = 0; rep < 4; rep++) {
        size_t i = base + (size_t)rep * 2097152;
        float4 f = reinterpret_cast<const float4*>(w2)[i];
        split4_store(&g_w2h[i * 4], &g_w2l[i * 4], f);
    }
}

// ---------------- kernel 2: route = count + prefix + scatter (one block) ----------------
__global__ void route_kernel() {
    __shared__ int sc[NEXP];
    __shared__ int so[NEXP];
    int tid = threadIdx.x;                 // 1024 threads
    if (tid < NEXP) sc[tid] = 0;
    __syncthreads();
    for (int i = tid; i < NPAIR; i += 1024) atomicAdd(&sc[g_topki[i]], 1);
    __syncthreads();
    if (tid == 0) {
        int s = 0;
#pragma unroll
        for (int e = 0; e < NEXP; e++) {
            so[e] = s;
            g_off[e] = s;
            g_cnt[e] = sc[e];
            s += sc[e];
        }
        g_off[NEXP] = s;
    }
    __syncthreads();
    if (tid < NEXP) sc[tid] = so[tid];
    __syncthreads();
    for (int i = tid; i < NPAIR; i += 1024) {
        int e = g_topki[i];
        int pos = atomicAdd(&sc[e], 1);
        g_pairs[pos] = i;
        g_pairof[i] = pos;
    }
}

// ---------------- kernel 3: gather x (split hi/lo) + (fused) W1 split ----------------
__global__ void gather_kernel(const float* __restrict__ x, const float* __restrict__ w1) {
    int pr = blockIdx.x;
    int tid = threadIdx.x;                 // 256 threads
    int tok = g_pairs[pr] >> 1;
    float4 f = reinterpret_cast<const float4*>(x + (size_t)tok * DIM)[tid];
    split4_store(&g_xh[(size_t)pr * DIM + tid * 4], &g_xl[(size_t)pr * DIM + tid * 4], f);

    size_t base = (size_t)pr * 256 + tid;
#pragma unroll
    for (int rep = 0; rep < 2; rep++) {
        size_t i = base + (size_t)rep * 4194304;
        float4 w = reinterpret_cast<const float4*>(w1)[i];
        split4_store(&g_w1h[i * 4], &g_w1l[i * 4], w);
    }
}

// ---------------- grouped GEMM: 128x128x32, 2 CTAs/SM, 2-stage cp.async -------------
// PASS1: g_h(hi/lo) = relu(Xg @ W1^T + b1)   K=1024, Nn=4096
// PASS2: g_y        =      H  @ W2^T + b2    K=4096, Nn=1024
#define BM 128
#define BN 128
#define BK 32
#define STR 40                      // 80B rows: conflict-free ldmatrix, 16B-aligned
#define PL (BM * STR)               // per-plane elems = 5120
#define BUF_ELEMS (4 * PL)          // Ah|Al|Bh|Bl = 20480 elems = 40960 B
#define SMEM_BYTES (2 * BUF_ELEMS * 2)   // 2 stages = 81920 B (-> 2 CTAs/SM)

template <bool PASS1>
__global__ __launch_bounds__(256, 2)
void moe_gemm(const float* __restrict__ Bias) {
    constexpr int K  = PASS1 ? DIM : HID;
    constexpr int Nn = PASS1 ? HID : DIM;
    constexpr int KT = K / BK;
    const __nv_bfloat16* __restrict__ Agh = PASS1 ? g_xh : g_hh;
    const __nv_bfloat16* __restrict__ Agl = PASS1 ? g_xl : g_hl;
    const __nv_bfloat16* __restrict__ Wgh = PASS1 ? g_w1h : g_w2h;
    const __nv_bfloat16* __restrict__ Wgl = PASS1 ? g_w1l : g_w2l;

    int e = blockIdx.z;
    int cnt = g_cnt[e];
    int m0 = blockIdx.x * BM;
    if (m0 >= cnt) return;
    int r0 = g_off[e] + m0;
    int n0 = blockIdx.y * BN;

    const __nv_bfloat16* We_h = Wgh + (size_t)e * Nn * K;
    const __nv_bfloat16* We_l = Wgl + (size_t)e * Nn * K;
    const float* be = Bias + (size_t)e * Nn;

    extern __shared__ __align__(16) unsigned char smem_raw[];
    __nv_bfloat16* smem = reinterpret_cast<__nv_bfloat16*>(smem_raw);

    int tid = threadIdx.x;
    int wid = tid >> 5, lane = tid & 31;
    int wm = wid & 3;        // 4 warps along M: 32 rows each
    int wn = wid >> 2;       // 2 warps along N: 64 cols each

    // stage loader: 2048 x 16B chunks, 8 per thread. planes: 0=Ah 1=Al 2=Bh 3=Bl
    auto load_panel = [&](int kt, int b) {
        const int k0 = kt * BK;
        __nv_bfloat16* bb = smem + b * BUF_ELEMS;
#pragma unroll
        for (int t = 0; t < 8; t++) {
            int id = tid + t * 256;
            int plane = id >> 9, rem = id & 511;
            int row = rem >> 2, ch = rem & 3;
            const __nv_bfloat16* src;
            if (plane == 0)      src = Agh  + (size_t)(r0 + row) * K + k0 + ch * 8;
            else if (plane == 1) src = Agl  + (size_t)(r0 + row) * K + k0 + ch * 8;
            else if (plane == 2) src = We_h + (size_t)(n0 + row) * K + k0 + ch * 8;
            else                 src = We_l + (size_t)(n0 + row) * K + k0 + ch * 8;
            cpa16(bb + plane * PL + row * STR + ch * 8, src);
        }
    };

    wmma::fragment<wmma::accumulator, 16, 16, 16, float> acc[2][4];
#pragma unroll
    for (int i = 0; i < 2; i++)
#pragma unroll
        for (int j = 0; j < 4; j++) wmma::fill_fragment(acc[i][j], 0.f);

    load_panel(0, 0);
    cp_commit();

    for (int kt = 0; kt < KT; kt++) {
        if (kt + 1 < KT) {
            load_panel(kt + 1, (kt + 1) & 1);
            cp_commit();
            cp_wait<1>();
        } else {
            cp_wait<0>();
        }
        __syncthreads();

        const __nv_bfloat16* bAh = smem + (kt & 1) * BUF_ELEMS;
        const __nv_bfloat16* bAl = bAh + PL;
        const __nv_bfloat16* bBh = bAh + 2 * PL;
        const __nv_bfloat16* bBl = bAh + 3 * PL;

#pragma unroll
        for (int kk = 0; kk < 2; kk++) {
            wmma::fragment<wmma::matrix_a, 16, 16, 16, __nv_bfloat16, wmma::row_major> ah[2], al[2];
#pragma unroll
            for (int i = 0; i < 2; i++) {
                wmma::load_matrix_sync(ah[i], bAh + (wm * 32 + i * 16) * STR + kk * 16, STR);
                wmma::load_matrix_sync(al[i], bAl + (wm * 32 + i * 16) * STR + kk * 16, STR);
            }
#pragma unroll
            for (int j = 0; j < 4; j++) {
                wmma::fragment<wmma::matrix_b, 16, 16, 16, __nv_bfloat16, wmma::col_major> bh, bl;
                wmma::load_matrix_sync(bh, bBh + (wn * 64 + j * 16) * STR + kk * 16, STR);
                wmma::load_matrix_sync(bl, bBl + (wn * 64 + j * 16) * STR + kk * 16, STR);
#pragma unroll
                for (int i = 0; i < 2; i++) {
                    wmma::mma_sync(acc[i][j], ah[i], bh, acc[i][j]);
                    wmma::mma_sync(acc[i][j], ah[i], bl, acc[i][j]);
                    wmma::mma_sync(acc[i][j], al[i], bh, acc[i][j]);
                }
            }
        }
        __syncthreads();
    }

    // epilogue: per-warp 32x64 fp32 stage in smem (8KB/warp, fits in the 80KB buffers)
    float* stage = reinterpret_cast<float*>(smem_raw) + (size_t)wid * 2048;
#pragma unroll
    for (int i = 0; i < 2; i++)
#pragma unroll
        for (int j = 0; j < 4; j++)
            wmma::store_matrix_sync(stage + i * 16 * 64 + j * 16, acc[i][j], 64,
                                    wmma::mem_row_major);
    __syncwarp();

    int rem = cnt - m0;   // valid rows in this tile
    for (int it = lane; it < 512; it += 32) {     // 32x64 elems as float4
        int row_loc = it >> 4;
        int c4 = (it & 15) * 4;
        int rtile = wm * 32 + row_loc;
        if (rtile < rem) {
            float4 v = *reinterpret_cast<float4*>(stage + row_loc * 64 + c4);
            int gcol = n0 + wn * 64 + c4;
            float4 bv = *reinterpret_cast<const float4*>(&be[gcol]);
            v.x += bv.x; v.y += bv.y; v.z += bv.z; v.w += bv.w;
            size_t grow = (size_t)(r0 + rtile);
            if (PASS1) {
                v.x = fmaxf(v.x, 0.f); v.y = fmaxf(v.y, 0.f);
                v.z = fmaxf(v.z, 0.f); v.w = fmaxf(v.w, 0.f);
                split4_store(&g_hh[grow * HID + gcol], &g_hl[grow * HID + gcol], v);
            } else {
                *reinterpret_cast<float4*>(&g_y[grow * DIM + gcol]) = v;
            }
        }
    }
}

// ---------------- kernel 6: combine + residual + LayerNorm ----------------
__global__ void finalize_kernel(const float* __restrict__ x,
                                const float* __restrict__ lnw,
                                const float* __restrict__ lnb,
                                float* __restrict__ out) {
    int t = blockIdx.x;
    int tid = threadIdx.x;
    int wid = tid >> 5, lane = tid & 31;

    float w0 = g_topkw[2 * t], w1 = g_topkw[2 * t + 1];
    size_t p0 = (size_t)g_pairof[2 * t] * DIM;
    size_t p1 = (size_t)g_pairof[2 * t + 1] * DIM;

    __shared__ float r[DIM];
    __shared__ float ps[8][2];

    float s = 0.f, s2 = 0.f;
    for (int i = tid; i < DIM; i += 256) {
        float v = x[(size_t)t * DIM + i] + w0 * g_y[p0 + i] + w1 * g_y[p1 + i];
        r[i] = v;
        s += v;
        s2 += v * v;
    }
#pragma unroll
    for (int o = 16; o > 0; o >>= 1) {
        s  += __shfl_down_sync(0xffffffffu, s, o);
        s2 += __shfl_down_sync(0xffffffffu, s2, o);
    }
    if (lane == 0) { ps[wid][0] = s; ps[wid][1] = s2; }
    __syncthreads();
    if (tid == 0) {
        float a = 0.f, b = 0.f;
#pragma unroll
        for (int w = 0; w < 8; w++) { a += ps[w][0]; b += ps[w][1]; }
        float mu = a / (float)DIM;
        float var = b / (float)DIM - mu * mu;
        ps[0][0] = mu;
        ps[0][1] = rsqrtf(var + LN_EPS);
    }
    __syncthreads();
    float mu = ps[0][0], inv = ps[0][1];
    for (int i = tid; i < DIM; i += 256)
        out[(size_t)t * DIM + i] = (r[i] - mu) * inv * lnw[i] + lnb[i];
}

// ---------------- launch ----------------
extern "C" void kernel_launch(void* const* d_in, const int* in_sizes, int n_in,
                              void* d_out, int out_size) {
    (void)in_sizes; (void)n_in; (void)out_size;
    const float* x   = (const float*)d_in[0];
    const float* gw  = (const float*)d_in[1];
    const float* gb  = (const float*)d_in[2];
    const float* w1  = (const float*)d_in[3];
    const float* b1  = (const float*)d_in[4];
    const float* w2  = (const float*)d_in[5];
    const float* b2  = (const float*)d_in[6];
    const float* lnw = (const float*)d_in[7];
    const float* lnb = (const float*)d_in[8];
    float* out = (float*)d_out;

    cudaFuncSetAttribute(moe_gemm<true>,  cudaFuncAttributeMaxDynamicSharedMemorySize, SMEM_BYTES);
    cudaFuncSetAttribute(moe_gemm<false>, cudaFuncAttributeMaxDynamicSharedMemorySize, SMEM_BYTES);

    gate_kernel<<<NTOK, 256>>>(x, gw, gb, w2);                         // launch 0 (+W2 split)
    route_kernel<<<1, 1024>>>();                                       // launch 1
    gather_kernel<<<NPAIR, 256>>>(x, w1);                              // launch 2 (+W1 split)
    moe_gemm<true><<<dim3(NPAIR / BM, HID / BN, NEXP), 256, SMEM_BYTES>>>(b1);   // launch 3 <- ncu
    moe_gemm<false><<<dim3(NPAIR / BM, DIM / BN, NEXP), 256, SMEM_BYTES>>>(b2);  // launch 4
    finalize_kernel<<<NTOK, 256>>>(x, lnw, lnb, out);                  // launch 5
}

// round 10
// speedup vs baseline: 2.9634x; 2.6323x over previous
#include <cuda_runtime.h>
#include <cuda_bf16.h>
#include <cuda_fp16.h>
#include <mma.h>
#include <math.h>
#include <cstdint>

using namespace nvcuda;

#define NTOK 8192
#define DIM  1024
#define HID  4096
#define NEXP 8
#define NPAIR (NTOK*2)
#define ROWPAD 128
#define LN_EPS 1e-5f

// ---------------- scratch (device globals) ----------------
__device__ float g_topkw[NPAIR];
__device__ int   g_topki[NPAIR];
__device__ int   g_cnt[NEXP];
__device__ int   g_off[NEXP + 1];
__device__ int   g_pairs[NPAIR];
__device__ int   g_pairof[NPAIR];

__device__ __half g_x16[(size_t)(NPAIR + ROWPAD) * DIM];
__device__ __half g_h16[(size_t)(NPAIR + ROWPAD) * HID];
__device__ __half g_w1_16[(size_t)NEXP * HID * DIM];
__device__ __half g_w2_16[(size_t)NEXP * DIM * HID];
__device__ float  g_y[(size_t)NPAIR * DIM];

// ---------------- helpers ----------------
__device__ __forceinline__ void cvt4_store(__half* dst, float4 f) {
    __half2 a = __floats2half2_rn(f.x, f.y);
    __half2 b = __floats2half2_rn(f.z, f.w);
    *reinterpret_cast<__half2*>(dst)     = a;
    *reinterpret_cast<__half2*>(dst + 2) = b;
}

__device__ __forceinline__ void cpa16(void* sdst, const void* gsrc) {
    uint32_t s = (uint32_t)__cvta_generic_to_shared(sdst);
    asm volatile("cp.async.cg.shared.global [%0], [%1], 16;\n" :: "r"(s), "l"(gsrc));
}
__device__ __forceinline__ void cp_commit() { asm volatile("cp.async.commit_group;\n"); }
template <int N> __device__ __forceinline__ void cp_wait() {
    asm volatile("cp.async.wait_group %0;\n" :: "n"(N));
}

// ---------------- kernel 1: gating + (fused) W2 -> fp16 ----------------
__global__ void gate_kernel(const float* __restrict__ x,
                            const float* __restrict__ gw,
                            const float* __restrict__ gb,
                            const float* __restrict__ w2) {
    int t = blockIdx.x;
    int tid = threadIdx.x;                 // 256 threads
    int wid = tid >> 5, lane = tid & 31;

    float acc[NEXP];
#pragma unroll
    for (int e = 0; e < NEXP; e++) acc[e] = 0.f;

    const float* xr = x + (size_t)t * DIM;
    for (int i = tid; i < DIM; i += 256) {
        float xv = xr[i];
#pragma unroll
        for (int e = 0; e < NEXP; e++) acc[e] += xv * gw[e * DIM + i];
    }
#pragma unroll
    for (int e = 0; e < NEXP; e++)
#pragma unroll
        for (int o = 16; o > 0; o >>= 1) acc[e] += __shfl_down_sync(0xffffffffu, acc[e], o);

    __shared__ float part[8][NEXP];
    if (lane == 0) {
#pragma unroll
        for (int e = 0; e < NEXP; e++) part[wid][e] = acc[e];
    }
    __syncthreads();

    if (tid == 0) {
        float lg[NEXP], p[NEXP];
#pragma unroll
        for (int e = 0; e < NEXP; e++) {
            float s = gb[e];
#pragma unroll
            for (int w = 0; w < 8; w++) s += part[w][e];
            lg[e] = s;
        }
        float m = lg[0];
#pragma unroll
        for (int e = 1; e < NEXP; e++) m = fmaxf(m, lg[e]);
        float se = 0.f;
#pragma unroll
        for (int e = 0; e < NEXP; e++) { p[e] = expf(lg[e] - m); se += p[e]; }
        float inv = 1.f / se;
#pragma unroll
        for (int e = 0; e < NEXP; e++) p[e] *= inv;

        int i0 = 0;
#pragma unroll
        for (int e = 1; e < NEXP; e++) if (p[e] > p[i0]) i0 = e;
        int i1 = (i0 == 0) ? 1 : 0;
#pragma unroll
        for (int e = 0; e < NEXP; e++) if (e != i0 && p[e] > p[i1]) i1 = e;

        float b = expf(p[i1] - p[i0]);
        float w0 = 1.f / (1.f + b);
        float w1 = b / (1.f + b);

        g_topki[2 * t]     = i0;  g_topki[2 * t + 1] = i1;
        g_topkw[2 * t]     = w0;  g_topkw[2 * t + 1] = w1;
    }

    // fused: convert W2 (8388608 float4) across 8192*256 threads, 4 each
    size_t base = (size_t)blockIdx.x * 256 + tid;
#pragma unroll
    for (int rep = 0; rep < 4; rep++) {
        size_t i = base + (size_t)rep * 2097152;
        float4 f = reinterpret_cast<const float4*>(w2)[i];
        cvt4_store(&g_w2_16[i * 4], f);
    }
}

// ---------------- kernel 2: route = count + prefix + scatter (one block) ----------------
__global__ void route_kernel() {
    __shared__ int sc[NEXP];
    __shared__ int so[NEXP];
    int tid = threadIdx.x;                 // 1024 threads
    if (tid < NEXP) sc[tid] = 0;
    __syncthreads();
    for (int i = tid; i < NPAIR; i += 1024) atomicAdd(&sc[g_topki[i]], 1);
    __syncthreads();
    if (tid == 0) {
        int s = 0;
#pragma unroll
        for (int e = 0; e < NEXP; e++) {
            so[e] = s;
            g_off[e] = s;
            g_cnt[e] = sc[e];
            s += sc[e];
        }
        g_off[NEXP] = s;
    }
    __syncthreads();
    if (tid < NEXP) sc[tid] = so[tid];
    __syncthreads();
    for (int i = tid; i < NPAIR; i += 1024) {
        int e = g_topki[i];
        int pos = atomicAdd(&sc[e], 1);
        g_pairs[pos] = i;
        g_pairof[i] = pos;
    }
}

// ---------------- kernel 3: gather x (fp16) + (fused) W1 -> fp16 ----------------
__global__ void gather_kernel(const float* __restrict__ x, const float* __restrict__ w1) {
    int pr = blockIdx.x;
    int tid = threadIdx.x;                 // 256 threads
    int tok = g_pairs[pr] >> 1;
    float4 f = reinterpret_cast<const float4*>(x + (size_t)tok * DIM)[tid];
    cvt4_store(&g_x16[(size_t)pr * DIM + tid * 4], f);

    size_t base = (size_t)pr * 256 + tid;
#pragma unroll
    for (int rep = 0; rep < 2; rep++) {
        size_t i = base + (size_t)rep * 4194304;
        float4 w = reinterpret_cast<const float4*>(w1)[i];
        cvt4_store(&g_w1_16[i * 4], w);
    }
}

// ---------------- grouped GEMM: fp16 single-plane, 128x128x64, 2 CTAs/SM ------------
// PASS1: g_h16 = relu(Xg @ W1^T + b1)   K=1024, Nn=4096
// PASS2: g_y   =      H  @ W2^T + b2    K=4096, Nn=1024
#define BM 128
#define BN 128
#define BK 64
#define STR 72                      // 144B rows: 16B-aligned, conflict-free LDSM phases
#define PL (BM * STR)               // per-plane elems = 9216
#define BUF_ELEMS (2 * PL)          // A|B = 18432 elems = 36864 B
#define SMEM_BYTES (2 * BUF_ELEMS * 2)   // 2 stages = 73728 B (-> 2 CTAs/SM)

template <bool PASS1>
__global__ __launch_bounds__(256, 2)
void moe_gemm(const float* __restrict__ Bias) {
    constexpr int K  = PASS1 ? DIM : HID;
    constexpr int Nn = PASS1 ? HID : DIM;
    constexpr int KT = K / BK;
    const __half* __restrict__ Ag = PASS1 ? g_x16 : g_h16;
    const __half* __restrict__ Wg = PASS1 ? g_w1_16 : g_w2_16;

    int e = blockIdx.z;
    int cnt = g_cnt[e];
    int m0 = blockIdx.x * BM;
    if (m0 >= cnt) return;
    int r0 = g_off[e] + m0;
    int n0 = blockIdx.y * BN;

    const __half* We = Wg + (size_t)e * Nn * K;
    const float* be = Bias + (size_t)e * Nn;

    extern __shared__ __align__(16) unsigned char smem_raw[];
    __half* smem = reinterpret_cast<__half*>(smem_raw);

    int tid = threadIdx.x;
    int wid = tid >> 5, lane = tid & 31;
    int wm = wid & 3;        // 4 warps along M: 32 rows each
    int wn = wid >> 2;       // 2 warps along N: 64 cols each

    // stage loader: 2048 x 16B chunks, 8 per thread. planes: 0=A 1=B
    auto load_panel = [&](int kt, int b) {
        const int k0 = kt * BK;
        __half* bb = smem + b * BUF_ELEMS;
#pragma unroll
        for (int t = 0; t < 8; t++) {
            int id = tid + t * 256;
            int plane = id >> 10, rem = id & 1023;
            int row = rem >> 3, ch = rem & 7;
            const __half* src = plane
                ? We + (size_t)(n0 + row) * K + k0 + ch * 8
                : Ag + (size_t)(r0 + row) * K + k0 + ch * 8;
            cpa16(bb + plane * PL + row * STR + ch * 8, src);
        }
    };

    wmma::fragment<wmma::accumulator, 16, 16, 16, float> acc[2][4];
#pragma unroll
    for (int i = 0; i < 2; i++)
#pragma unroll
        for (int j = 0; j < 4; j++) wmma::fill_fragment(acc[i][j], 0.f);

    load_panel(0, 0);
    cp_commit();

    for (int kt = 0; kt < KT; kt++) {
        if (kt + 1 < KT) {
            load_panel(kt + 1, (kt + 1) & 1);
            cp_commit();
            cp_wait<1>();
        } else {
            cp_wait<0>();
        }
        __syncthreads();

        const __half* bA = smem + (kt & 1) * BUF_ELEMS;
        const __half* bB = bA + PL;

#pragma unroll
        for (int kk = 0; kk < 4; kk++) {
            wmma::fragment<wmma::matrix_a, 16, 16, 16, __half, wmma::row_major> a[2];
#pragma unroll
            for (int i = 0; i < 2; i++)
                wmma::load_matrix_sync(a[i], bA + (wm * 32 + i * 16) * STR + kk * 16, STR);
#pragma unroll
            for (int j = 0; j < 4; j++) {
                wmma::fragment<wmma::matrix_b, 16, 16, 16, __half, wmma::col_major> bf;
                wmma::load_matrix_sync(bf, bB + (wn * 64 + j * 16) * STR + kk * 16, STR);
#pragma unroll
                for (int i = 0; i < 2; i++)
                    wmma::mma_sync(acc[i][j], a[i], bf, acc[i][j]);
            }
        }
        __syncthreads();
    }

    // epilogue: per-warp 32x64 fp32 stage in smem (8KB/warp)
    float* stage = reinterpret_cast<float*>(smem_raw) + (size_t)wid * 2048;
#pragma unroll
    for (int i = 0; i < 2; i++)
#pragma unroll
        for (int j = 0; j < 4; j++)
            wmma::store_matrix_sync(stage + i * 16 * 64 + j * 16, acc[i][j], 64,
                                    wmma::mem_row_major);
    __syncwarp();

    int rem = cnt - m0;   // valid rows in this tile
    for (int it = lane; it < 512; it += 32) {     // 32x64 elems as float4
        int row_loc = it >> 4;
        int c4 = (it & 15) * 4;
        int rtile = wm * 32 + row_loc;
        if (rtile < rem) {
            float4 v = *reinterpret_cast<float4*>(stage + row_loc * 64 + c4);
            int gcol = n0 + wn * 64 + c4;
            float4 bv = *reinterpret_cast<const float4*>(&be[gcol]);
            v.x += bv.x; v.y += bv.y; v.z += bv.z; v.w += bv.w;
            size_t grow = (size_t)(r0 + rtile);
            if (PASS1) {
                v.x = fmaxf(v.x, 0.f); v.y = fmaxf(v.y, 0.f);
                v.z = fmaxf(v.z, 0.f); v.w = fmaxf(v.w, 0.f);
                cvt4_store(&g_h16[grow * HID + gcol], v);
            } else {
                *reinterpret_cast<float4*>(&g_y[grow * DIM + gcol]) = v;
            }
        }
    }
}

// ---------------- kernel 6: combine + residual + LayerNorm ----------------
__global__ void finalize_kernel(const float* __restrict__ x,
                                const float* __restrict__ lnw,
                                const float* __restrict__ lnb,
                                float* __restrict__ out) {
    int t = blockIdx.x;
    int tid = threadIdx.x;
    int wid = tid >> 5, lane = tid & 31;

    float w0 = g_topkw[2 * t], w1 = g_topkw[2 * t + 1];
    size_t p0 = (size_t)g_pairof[2 * t] * DIM;
    size_t p1 = (size_t)g_pairof[2 * t + 1] * DIM;

    __shared__ float r[DIM];
    __shared__ float ps[8][2];

    float s = 0.f, s2 = 0.f;
    for (int i = tid; i < DIM; i += 256) {
        float v = x[(size_t)t * DIM + i] + w0 * g_y[p0 + i] + w1 * g_y[p1 + i];
        r[i] = v;
        s += v;
        s2 += v * v;
    }
#pragma unroll
    for (int o = 16; o > 0; o >>= 1) {
        s  += __shfl_down_sync(0xffffffffu, s, o);
        s2 += __shfl_down_sync(0xffffffffu, s2, o);
    }
    if (lane == 0) { ps[wid][0] = s; ps[wid][1] = s2; }
    __syncthreads();
    if (tid == 0) {
        float a = 0.f, b = 0.f;
#pragma unroll
        for (int w = 0; w < 8; w++) { a += ps[w][0]; b += ps[w][1]; }
        float mu = a / (float)DIM;
        float var = b / (float)DIM - mu * mu;
        ps[0][0] = mu;
        ps[0][1] = rsqrtf(var + LN_EPS);
    }
    __syncthreads();
    float mu = ps[0][0], inv = ps[0][1];
    for (int i = tid; i < DIM; i += 256)
        out[(size_t)t * DIM + i] = (r[i] - mu) * inv * lnw[i] + lnb[i];
}

// ---------------- launch ----------------
extern "C" void kernel_launch(void* const* d_in, const int* in_sizes, int n_in,
                              void* d_out, int out_size) {
    (void)in_sizes; (void)n_in; (void)out_size;
    const float* x   = (const float*)d_in[0];
    const float* gw  = (const float*)d_in[1];
    const float* gb  = (const float*)d_in[2];
    const float* w1  = (const float*)d_in[3];
    const float* b1  = (const float*)d_in[4];
    const float* w2  = (const float*)d_in[5];
    const float* b2  = (const float*)d_in[6];
    const float* lnw = (const float*)d_in[7];
    const float* lnb = (const float*)d_in[8];
    float* out = (float*)d_out;

    cudaFuncSetAttribute(moe_gemm<true>,  cudaFuncAttributeMaxDynamicSharedMemorySize, SMEM_BYTES);
    cudaFuncSetAttribute(moe_gemm<false>, cudaFuncAttributeMaxDynamicSharedMemorySize, SMEM_BYTES);

    gate_kernel<<<NTOK, 256>>>(x, gw, gb, w2);                         // launch 0 (+W2 cvt)
    route_kernel<<<1, 1024>>>();                                       // launch 1
    gather_kernel<<<NPAIR, 256>>>(x, w1);                              // launch 2 (+W1 cvt)
    moe_gemm<true><<<dim3(NPAIR / BM, HID / BN, NEXP), 256, SMEM_BYTES>>>(b1);   // launch 3 <- ncu
    moe_gemm<false><<<dim3(NPAIR / BM, DIM / BN, NEXP), 256, SMEM_BYTES>>>(b2);  // launch 4
    finalize_kernel<<<NTOK, 256>>>(x, lnw, lnb, out);                  // launch 5
}